// round 14
// baseline (speedup 1.0000x reference)
#include <cuda_runtime.h>
#include <cuda_fp16.h>
#include <cstdint>

// ---------------------------------------------------------------------------
// GroupedLinear: y[b, g*256+o] = sum_i x[b, g*256+i] * W[g,o,i] + bias[g,o]
// 16 independent GEMMs: M=8192, N=256, K=256, fp32 in/out.
//
// R13: 72.4us total (main 68.5), tensor 41%, L1 56%, occ 12.6% -> latency/
// convoy exposure at 8 warps/SM; RF blocks 2 CTA/SM at 245 regs.
// R14: 16 warps in ONE 512-thread CTA, same 128x256 CTA tile; warp grid
// 2(M) x 8(N), warp tile 64x32 -> acc 64 regs, ~128 regs total (RF-exact).
// Sector-perfect loaders remapped for 512 threads. Everything else = R13.
// ---------------------------------------------------------------------------

namespace gl {

constexpr int INF  = 4096;
constexpr int NG   = 16;
constexpr int GIN  = 256;          // K per group
constexpr int GOUT = 256;          // N per group
constexpr int MT   = 128;          // CTA M tile
constexpr int NT   = 256;          // CTA N tile (full group)
constexpr int KCH  = 64;           // K chunk: 64 halves = 128 B rows
constexpr int NCHUNK = 4;          // K chunks per tile (256/64)
constexpr int TILES = 1024;        // 16 groups x 64 m-tiles
constexpr int NCTA  = 152;         // 1 CTA per SM (GB300: 152 SMs)
constexpr int NTHREADS = 512;      // 16 warps, 2(M) x 8(N), warp tile 64x32

constexpr int A_BYTES = MT * KCH * 2;           // 16 KB per stage
constexpr int B_BYTES = NT * KCH * 2;           // 32 KB per stage
constexpr int STAGE_BYTES = A_BYTES + B_BYTES;  // 48 KB

constexpr int OFF_STAGE = 1024;
constexpr int SMEM_TOTAL = OFF_STAGE + 3 * STAGE_BYTES;  // 148480 B

__device__ __forceinline__ uint32_t swz(uint32_t x) {
    return x ^ ((x >> 3) & 0x70);
}

__device__ __forceinline__ void cp16(uint32_t dst, const void* src) {
    asm volatile("cp.async.cg.shared.global [%0], [%1], 16;"
                 :: "r"(dst), "l"(src) : "memory");
}

__device__ __forceinline__ uint32_t smem_u32(const void* p) {
    uint32_t a;
    asm("{ .reg .u64 t; cvta.to.shared.u64 t, %1; cvt.u32.u64 %0, t; }"
        : "=r"(a) : "l"(p));
    return a;
}

__device__ __forceinline__ void ldsm4(uint32_t& r0, uint32_t& r1,
                                      uint32_t& r2, uint32_t& r3,
                                      uint32_t addr) {
    asm volatile("ldmatrix.sync.aligned.m8n8.x4.shared.b16 {%0,%1,%2,%3}, [%4];"
                 : "=r"(r0), "=r"(r1), "=r"(r2), "=r"(r3) : "r"(addr));
}

__device__ __forceinline__ void mma_f16(float* c,
                                        uint32_t a0, uint32_t a1,
                                        uint32_t a2, uint32_t a3,
                                        uint32_t b0, uint32_t b1) {
    asm volatile(
        "mma.sync.aligned.m16n8k16.row.col.f32.f16.f16.f32 "
        "{%0,%1,%2,%3}, {%4,%5,%6,%7}, {%8,%9}, {%0,%1,%2,%3};"
        : "+f"(c[0]), "+f"(c[1]), "+f"(c[2]), "+f"(c[3])
        : "r"(a0), "r"(a1), "r"(a2), "r"(a3), "r"(b0), "r"(b1));
}

__device__ __forceinline__ uint32_t h2u(__half2 h) {
    return *reinterpret_cast<uint32_t*>(&h);
}

} // namespace gl

using namespace gl;

// fp16 copy of W (2MB), produced once per launch (idempotent, deterministic).
__device__ __half g_Wh[NG * GOUT * GIN];

__global__ __launch_bounds__(256, 8)
void GroupedLinear_cvtW_kernel(const float4* __restrict__ in,
                               uint2* __restrict__ out, int n4) {
    const int stride = gridDim.x * 256;
    for (int i = blockIdx.x * 256 + threadIdx.x; i < n4; i += stride) {
        float4 v = in[i];
        __half2 lo = __floats2half2_rn(v.x, v.y);
        __half2 hi = __floats2half2_rn(v.z, v.w);
        uint2 o;
        o.x = *reinterpret_cast<uint32_t*>(&lo);
        o.y = *reinterpret_cast<uint32_t*>(&hi);
        out[i] = o;
    }
}

__global__ __launch_bounds__(NTHREADS, 1)
void GroupedLinear_35364760715975_kernel(const float* __restrict__ x,
                                         const float* __restrict__ bias,
                                         float* __restrict__ y)
{
    extern __shared__ char smem[];
    const uint32_t sbase = smem_u32(smem);
    const int tid = threadIdx.x;
    const int bid = blockIdx.x;

    // ---- loader lane geometry (512 threads) ----
    const int lrr = tid >> 3;        // row 0..63
    const int lss = tid & 7;         // 16B fp16 slot (= 32B fp32 slot)

    // B loader (cp.async from g_Wh): 4 iters x 64 rows = 256 rows
    uint32_t dstoB[4];
    #pragma unroll
    for (int i = 0; i < 4; i++)
        dstoB[i] = swz((uint32_t)((lrr + i * 64) * 128 + lss * 16));

    auto loadB = [&](int q, int buf) {
        const int t  = q >> 2;
        const int kc = q & 3;
        const int g  = (bid + t * NCTA) >> 6;
        const __half* ws = g_Wh + (size_t)g * GOUT * GIN
                                + (size_t)lrr * GIN + kc * KCH + lss * 8;
        const uint32_t bbase = sbase + OFF_STAGE + buf * STAGE_BYTES + A_BYTES;
        #pragma unroll
        for (int i = 0; i < 4; i++)
            cp16(bbase + dstoB[i], ws + (size_t)(i * 64) * GIN);
    };

    // A loader: sector-perfect LDG fp32 (8 contiguous floats = full 32B sector)
    // 2 iters x 64 rows = 128 rows
    uint32_t astso[2];
    #pragma unroll
    for (int i = 0; i < 2; i++)
        astso[i] = swz((uint32_t)((lrr + i * 64) * 128 + lss * 16));

    float4 ldgbuf[4];                // 2 rows x 2 float4

    auto ldgA = [&](int q) {
        const int t    = q >> 2;
        const int kc   = q & 3;
        const int tile = bid + t * NCTA;
        const int g    = tile >> 6;
        const int mt   = tile & 63;
        const float* base = x + (size_t)(mt * MT + lrr) * INF
                              + g * GIN + kc * KCH + lss * 8;
        #pragma unroll
        for (int i = 0; i < 2; i++) {
            const float4* p = (const float4*)(base + (size_t)(i * 64) * INF);
            ldgbuf[2 * i]     = p[0];
            ldgbuf[2 * i + 1] = p[1];
        }
    };

    auto stsA = [&](int buf) {
        const uint32_t ab = sbase + OFF_STAGE + buf * STAGE_BYTES;
        #pragma unroll
        for (int i = 0; i < 2; i++) {
            uint32_t h0 = h2u(__floats2half2_rn(ldgbuf[2*i].x,   ldgbuf[2*i].y));
            uint32_t h1 = h2u(__floats2half2_rn(ldgbuf[2*i].z,   ldgbuf[2*i].w));
            uint32_t h2 = h2u(__floats2half2_rn(ldgbuf[2*i+1].x, ldgbuf[2*i+1].y));
            uint32_t h3 = h2u(__floats2half2_rn(ldgbuf[2*i+1].z, ldgbuf[2*i+1].w));
            asm volatile("st.shared.v4.b32 [%0], {%1,%2,%3,%4};"
                         :: "r"(ab + astso[i]), "r"(h0), "r"(h1), "r"(h2), "r"(h3)
                         : "memory");
        }
    };

    // tiles for this CTA: bid, bid+NCTA, ...
    const int ntiles = (TILES - 1 - bid) / NCTA + 1;
    const int qtot = ntiles * NCHUNK;

    // ---- prologue ----
    ldgA(0);
    stsA(0);
    loadB(0, 0); asm volatile("cp.async.commit_group;" ::: "memory");
    ldgA(1);
    loadB(1, 1); asm volatile("cp.async.commit_group;" ::: "memory");

    // ---- per-warp geometry: 2(M) x 8(N) warps, warp tile 64x32 ----
    const int wid  = tid >> 5;
    const int lane = tid & 31;
    const int wm = wid >> 3;          // 0..1
    const int wn = wid & 7;           // 0..7
    const int grp = lane >> 2;        // 0..7
    const int tig = lane & 3;         // 0..3
    const int kk0 = wid & 3;          // stagger k-step order per warp

    // ldmatrix lane geometry (b16, canonical m16n8k16 fragments)
    const int q8 = lane >> 3;         // 0..3
    const int i8 = lane & 7;          // 0..7
    const uint32_t ix = (uint32_t)i8 << 4;
    const uint32_t aq16 = (uint32_t)((q8 >> 1) << 4);
    const uint32_t arow = (uint32_t)(((q8 & 1) * 8 + i8) * 128) + (uint32_t)(wm << 13);
    const uint32_t bq16 = (uint32_t)((q8 & 1) << 4);
    const uint32_t brow = (uint32_t)(((q8 >> 1) * 8 + i8) * 128) + (uint32_t)(wn << 12);

    float acc[4][4][4];               // [m16-tile][n8-tile][reg] = 64 regs
    #pragma unroll
    for (int a = 0; a < 4; a++)
        #pragma unroll
        for (int b = 0; b < 4; b++)
            #pragma unroll
            for (int c = 0; c < 4; c++) acc[a][b][c] = 0.f;

    // ---- flat persistent mainloop over (tile, k64-chunk) ----
    int buf = 0;                      // q % 3
    #pragma unroll 1
    for (int q = 0; q < qtot; q++) {
        asm volatile("cp.async.wait_group 1;" ::: "memory");
        __syncthreads();   // stage q (A STS + B cp.async) visible

        if (q + 1 < qtot) stsA((buf == 2) ? 0 : buf + 1);
        if (q + 2 < qtot) {
            ldgA(q + 2);
            loadB(q + 2, (buf == 0) ? 2 : buf - 1);
            asm volatile("cp.async.commit_group;" ::: "memory");
        } else {
            asm volatile("cp.async.commit_group;" ::: "memory"); // uniform count
        }

        const uint32_t stage = sbase + OFF_STAGE + buf * STAGE_BYTES;
        const uint32_t Arow = stage + arow;
        const uint32_t Brow = stage + A_BYTES + brow;

        #pragma unroll
        for (int j = 0; j < 4; j++) {
            const int kk = (j + kk0) & 3;           // k16 step within k64 row
            const uint32_t cxA = ((uint32_t)(kk * 32) + aq16) ^ ix;
            const uint32_t cxB = ((uint32_t)(kk * 32) + bq16) ^ ix;

            // A fragments: 4 m16 tiles (64 rows)
            uint32_t af[4][4];
            #pragma unroll
            for (int mti = 0; mti < 4; mti++)
                ldsm4(af[mti][0], af[mti][1], af[mti][2], af[mti][3],
                      Arow + (uint32_t)(mti * 2048) + cxA);

            // B fragments: 4 n8 tiles (32 rows), 2 ldmatrix.x4
            uint32_t bf[4][2];
            ldsm4(bf[0][0], bf[0][1], bf[1][0], bf[1][1], Brow + cxB);
            ldsm4(bf[2][0], bf[2][1], bf[3][0], bf[3][1], Brow + 2048u + cxB);

            // 16 MMAs
            #pragma unroll
            for (int mti = 0; mti < 4; mti++)
                #pragma unroll
                for (int nti = 0; nti < 4; nti++)
                    mma_f16(acc[mti][nti],
                            af[mti][0], af[mti][1], af[mti][2], af[mti][3],
                            bf[nti][0], bf[nti][1]);
        }

        // ---- tile boundary: barrier-free inline epilogue ----
        if ((q & 3) == 3) {
            const int tile = bid + (q >> 2) * NCTA;
            const int g    = tile >> 6;
            const int m0   = (tile & 63) * MT;
            const int gb   = g * GOUT;

            const float* bp = bias + gb + wn * 32 + tig * 2;
            float2 bv[4];
            #pragma unroll
            for (int nti = 0; nti < 4; nti++)
                bv[nti] = *(const float2*)(bp + nti * 8);

            #pragma unroll
            for (int mti = 0; mti < 4; mti++) {
                const int row0 = m0 + wm * 64 + mti * 16 + grp;
                float* yr0 = y + (size_t)row0 * INF + gb + wn * 32 + tig * 2;
                float* yr1 = yr0 + (size_t)8 * INF;
                #pragma unroll
                for (int nti = 0; nti < 4; nti++) {
                    float2 v0, v1;
                    v0.x = acc[mti][nti][0] + bv[nti].x;
                    v0.y = acc[mti][nti][1] + bv[nti].y;
                    v1.x = acc[mti][nti][2] + bv[nti].x;
                    v1.y = acc[mti][nti][3] + bv[nti].y;
                    *(float2*)(yr0 + nti * 8) = v0;
                    *(float2*)(yr1 + nti * 8) = v1;
                    acc[mti][nti][0] = 0.f; acc[mti][nti][1] = 0.f;
                    acc[mti][nti][2] = 0.f; acc[mti][nti][3] = 0.f;
                }
            }
        }

        buf = (buf == 2) ? 0 : buf + 1;
    }
}

extern "C" void kernel_launch(void* const* d_in, const int* in_sizes, int n_in,
                              void* d_out, int out_size) {
    const float* x  = (const float*)d_in[0];
    const float* Wt = (const float*)d_in[1];
    const float* b  = (const float*)d_in[2];
    float* y = (float*)d_out;

    cudaFuncSetAttribute(GroupedLinear_35364760715975_kernel,
                         cudaFuncAttributeMaxDynamicSharedMemorySize, SMEM_TOTAL);

    // 1) convert W (1M f32) to fp16 rne (~1us)
    __half* wh_dev = nullptr;
    cudaGetSymbolAddress((void**)&wh_dev, g_Wh);
    GroupedLinear_cvtW_kernel<<<256, 256>>>((const float4*)Wt,
                                            (uint2*)wh_dev, NG * GOUT * GIN / 4);

    // 2) persistent fused cvt+GEMM: 152 CTAs (1 per SM on GB300), 512 thr
    GroupedLinear_35364760715975_kernel<<<NCTA, NTHREADS, SMEM_TOTAL>>>(x, b, y);
}